// round 1
// baseline (speedup 1.0000x reference)
#include <cuda_runtime.h>
#include <math.h>

#define B 64
#define S 512
#define H 1024
#define E 10
#define G4 4096
#define LSTM_IN 1035

// output packing offsets (flattened pytree order)
#define OFF_FIN 0
#define OFF_H   64
#define OFF_C   (64 + B*H)            // 65600
#define OFF_A   (64 + 2*B*H)          // 131136
#define OFF_S   (64 + 2*B*H + B*S)    // 163904

// scratch (no allocation allowed)
__device__ float g_dec_proj[B*H];
__device__ float g_scores[B*S];
__device__ float g_context[B*H];
__device__ float g_gates[B*G4];
__device__ float g_sim[B*E];

__device__ __forceinline__ float sigmoidf_(float x) { return 1.f / (1.f + expf(-x)); }

// ---------------------------------------------------------------------------
// Zero the atomically-accumulated buffers
// ---------------------------------------------------------------------------
__global__ void k_zero() {
    int i = blockIdx.x * blockDim.x + threadIdx.x;
    if (i < B*H) g_dec_proj[i] = 0.f;
    if (i < B*S) g_scores[i] = 0.f;
}

// ---------------------------------------------------------------------------
// Generic 64-row GEMM: C[64, N] += A[64, K] * W[N, ldw]^T  over k in block's chunk
// grid = (N/64, K/kChunk), block = 256.  Thread tile 4x4.
// Scalar loads (ldw may be odd, e.g. 1035 for W_ih).
// ---------------------------------------------------------------------------
__global__ void __launch_bounds__(256) k_gemm64(
    const float* __restrict__ A, int lda,
    const float* __restrict__ W, int ldw,
    float* __restrict__ C, int ldc,
    int kChunk, int K)
{
    __shared__ float As[16][68];
    __shared__ float Ws[16][68];
    int tid = threadIdx.x;
    int nBase = blockIdx.x * 64;
    int kb = blockIdx.y * kChunk;
    int ke = min(kb + kChunk, K);
    int tx = tid & 15, ty = tid >> 4;
    int lm = tid >> 2;
    int lk = (tid & 3) * 4;

    float acc[4][4];
#pragma unroll
    for (int i = 0; i < 4; i++)
#pragma unroll
        for (int j = 0; j < 4; j++) acc[i][j] = 0.f;

    for (int k0 = kb; k0 < ke; k0 += 16) {
#pragma unroll
        for (int j = 0; j < 4; j++)
            As[lk + j][lm] = A[(size_t)lm * lda + k0 + lk + j];
#pragma unroll
        for (int j = 0; j < 4; j++)
            Ws[lk + j][lm] = W[(size_t)(nBase + lm) * ldw + k0 + lk + j];
        __syncthreads();
#pragma unroll
        for (int kk = 0; kk < 16; kk++) {
            float a[4], w[4];
#pragma unroll
            for (int i = 0; i < 4; i++) a[i] = As[kk][ty*4 + i];
#pragma unroll
            for (int j = 0; j < 4; j++) w[j] = Ws[kk][tx*4 + j];
#pragma unroll
            for (int i = 0; i < 4; i++)
#pragma unroll
                for (int j = 0; j < 4; j++) acc[i][j] += a[i] * w[j];
        }
        __syncthreads();
    }
#pragma unroll
    for (int i = 0; i < 4; i++)
#pragma unroll
        for (int j = 0; j < 4; j++)
            atomicAdd(&C[(size_t)(ty*4 + i) * ldc + nBase + tx*4 + j], acc[i][j]);
}

// ---------------------------------------------------------------------------
// Fused attention-score GEMM:
//   scores[b,s] += sum_{g in tile} w_val[g] * tanh( dec_proj[b,g] +
//                       sum_h W_enc[g,h] * enc[b,s,h] )
// grid = (B*S/128, H/64), block = 256.  C-tile 128x64, thread tile 8x4.
// ---------------------------------------------------------------------------
__global__ void __launch_bounds__(256) k_attn_scores(
    const float* __restrict__ enc,
    const float* __restrict__ W_enc,
    const float* __restrict__ w_val)
{
    __shared__ float Es[16][132];
    __shared__ float Ws[16][68];
    int tid = threadIdx.x;
    int rowBase = blockIdx.x * 128;   // bs-row tile (always within one batch b)
    int gBase   = blockIdx.y * 64;
    int tx = tid & 15, ty = tid >> 4;
    int lm = tid >> 2;                // 0..63
    int lk = (tid & 3) * 4;           // 0,4,8,12

    float acc[8][4];
#pragma unroll
    for (int i = 0; i < 8; i++)
#pragma unroll
        for (int j = 0; j < 4; j++) acc[i][j] = 0.f;

    const float* encBase = enc + (size_t)rowBase * H;

    for (int k0 = 0; k0 < H; k0 += 16) {
        float4 v0 = *(const float4*)(encBase + (size_t)lm        * H + k0 + lk);
        float4 v1 = *(const float4*)(encBase + (size_t)(lm + 64) * H + k0 + lk);
        Es[lk+0][lm]      = v0.x; Es[lk+1][lm]      = v0.y;
        Es[lk+2][lm]      = v0.z; Es[lk+3][lm]      = v0.w;
        Es[lk+0][lm + 64] = v1.x; Es[lk+1][lm + 64] = v1.y;
        Es[lk+2][lm + 64] = v1.z; Es[lk+3][lm + 64] = v1.w;
        float4 w4 = *(const float4*)(W_enc + (size_t)(gBase + lm) * H + k0 + lk);
        Ws[lk+0][lm] = w4.x; Ws[lk+1][lm] = w4.y;
        Ws[lk+2][lm] = w4.z; Ws[lk+3][lm] = w4.w;
        __syncthreads();
#pragma unroll
        for (int kk = 0; kk < 16; kk++) {
            float a[8], w[4];
#pragma unroll
            for (int i = 0; i < 8; i++) a[i] = Es[kk][ty*8 + i];
#pragma unroll
            for (int j = 0; j < 4; j++) w[j] = Ws[kk][tx*4 + j];
#pragma unroll
            for (int i = 0; i < 8; i++)
#pragma unroll
                for (int j = 0; j < 4; j++) acc[i][j] += a[i] * w[j];
        }
        __syncthreads();
    }

    // epilogue: tanh + w_val dot, reduce over g within tile
    int b = rowBase / S;
    float wv[4], dp[4];
#pragma unroll
    for (int j = 0; j < 4; j++) {
        int g = gBase + tx*4 + j;
        wv[j] = w_val[g];
        dp[j] = g_dec_proj[b*H + g];
    }
#pragma unroll
    for (int i = 0; i < 8; i++) {
        float p = 0.f;
#pragma unroll
        for (int j = 0; j < 4; j++)
            p += wv[j] * tanhf(acc[i][j] + dp[j]);
        // reduce across the 16 tx lanes (contiguous within half-warp)
#pragma unroll
        for (int off = 8; off > 0; off >>= 1)
            p += __shfl_down_sync(0xffffffffu, p, off, 16);
        if (tx == 0)
            atomicAdd(&g_scores[rowBase + ty*8 + i], p);
    }
}

// ---------------------------------------------------------------------------
// Softmax over s, writes attn_weight into d_out.  grid=B, block=256 (2 s each)
// ---------------------------------------------------------------------------
__global__ void k_softmax(float* __restrict__ out)
{
    int b = blockIdx.x, tid = threadIdx.x;
    __shared__ float red[256];
    float s0 = g_scores[b*S + tid];
    float s1 = g_scores[b*S + 256 + tid];
    red[tid] = fmaxf(s0, s1);
    __syncthreads();
    for (int off = 128; off > 0; off >>= 1) {
        if (tid < off) red[tid] = fmaxf(red[tid], red[tid + off]);
        __syncthreads();
    }
    float m = red[0];
    __syncthreads();
    float e0 = expf(s0 - m), e1 = expf(s1 - m);
    red[tid] = e0 + e1;
    __syncthreads();
    for (int off = 128; off > 0; off >>= 1) {
        if (tid < off) red[tid] += red[tid + off];
        __syncthreads();
    }
    float inv = 1.f / red[0];
    out[OFF_A + b*S + tid]       = e0 * inv;
    out[OFF_A + b*S + 256 + tid] = e1 * inv;
}

// ---------------------------------------------------------------------------
// context[b,h] = sum_s attn[b,s] * enc[b,s,h].  grid=(B, H/256), block=256
// ---------------------------------------------------------------------------
__global__ void k_context(const float* __restrict__ enc, const float* __restrict__ out)
{
    int b = blockIdx.x;
    int h = blockIdx.y * 256 + threadIdx.x;
    __shared__ float w[S];
    for (int s = threadIdx.x; s < S; s += 256) w[s] = out[OFF_A + b*S + s];
    __syncthreads();
    const float* p = enc + (size_t)b * S * H + h;
    float a0 = 0.f, a1 = 0.f, a2 = 0.f, a3 = 0.f;
#pragma unroll 4
    for (int s = 0; s < S; s += 4) {
        a0 += w[s]     * p[(size_t)s * H];
        a1 += w[s + 1] * p[(size_t)(s + 1) * H];
        a2 += w[s + 2] * p[(size_t)(s + 2) * H];
        a3 += w[s + 3] * p[(size_t)(s + 3) * H];
    }
    g_context[b*H + h] = (a0 + a1) + (a2 + a3);
}

// ---------------------------------------------------------------------------
// sim = (context @ events^T) @ W_gate^T.  grid=B, block=320 (one warp per event)
// ---------------------------------------------------------------------------
__global__ void k_sim(const float* __restrict__ events,
                      const float* __restrict__ W_gate,
                      float* __restrict__ out)
{
    int b = blockIdx.x;
    int tid = threadIdx.x, warp = tid >> 5, lane = tid & 31;
    __shared__ float t[E];
    if (warp < E) {
        float acc = 0.f;
        for (int h = lane; h < H; h += 32)
            acc += g_context[b*H + h] * events[warp*H + h];
#pragma unroll
        for (int off = 16; off > 0; off >>= 1)
            acc += __shfl_down_sync(0xffffffffu, acc, off);
        if (lane == 0) t[warp] = acc;
    }
    __syncthreads();
    if (tid < E) {
        float s = 0.f;
#pragma unroll
        for (int e = 0; e < E; e++) s += t[e] * W_gate[tid*E + e];
        g_sim[b*E + tid] = s;
        out[OFF_S + b*E + tid] = s;
    }
}

// ---------------------------------------------------------------------------
// gates[b,j] = b_ih[j] + b_hh[j] + x[b]*W_ih[j,1034] + sum_e sim[b,e]*W_ih[j,1024+e]
// grid=(B, 16), block=256
// ---------------------------------------------------------------------------
__global__ void k_gates_init(const float* __restrict__ x,
                             const float* __restrict__ W_ih,
                             const float* __restrict__ b_ih,
                             const float* __restrict__ b_hh)
{
    int b = blockIdx.x;
    int j = blockIdx.y * 256 + threadIdx.x;
    const float* wr = W_ih + (size_t)j * LSTM_IN;
    float v = b_ih[j] + b_hh[j] + x[b] * wr[1034];
#pragma unroll
    for (int e = 0; e < E; e++) v += g_sim[b*E + e] * wr[1024 + e];
    g_gates[b*G4 + j] = v;
}

// ---------------------------------------------------------------------------
// LSTM elementwise + LayerNorm + final projection.  grid=B, block=256 (4 h each)
// ---------------------------------------------------------------------------
__global__ void k_lstm_final(const float* __restrict__ c0,
                             const float* __restrict__ ln_g,
                             const float* __restrict__ ln_b,
                             const float* __restrict__ W_fin,
                             const float* __restrict__ b_fin,
                             float* __restrict__ out)
{
    int b = blockIdx.x, tid = threadIdx.x;
    __shared__ float red[256];
    float hv[4];
    float sum = 0.f;
#pragma unroll
    for (int r = 0; r < 4; r++) {
        int h = r*256 + tid;
        float ig = g_gates[b*G4 + h];
        float fg = g_gates[b*G4 + 1024 + h];
        float gg = g_gates[b*G4 + 2048 + h];
        float og = g_gates[b*G4 + 3072 + h];
        float cn = sigmoidf_(fg) * c0[b*H + h] + sigmoidf_(ig) * tanhf(gg);
        float hn = sigmoidf_(og) * tanhf(cn);
        out[OFF_H + b*H + h] = hn;
        out[OFF_C + b*H + h] = cn;
        hv[r] = hn;
        sum += hn;
    }
    red[tid] = sum; __syncthreads();
    for (int off = 128; off > 0; off >>= 1) {
        if (tid < off) red[tid] += red[tid + off];
        __syncthreads();
    }
    float mu = red[0] * (1.f / H);
    __syncthreads();
    float sq = 0.f;
#pragma unroll
    for (int r = 0; r < 4; r++) { float d = hv[r] - mu; sq += d * d; }
    red[tid] = sq; __syncthreads();
    for (int off = 128; off > 0; off >>= 1) {
        if (tid < off) red[tid] += red[tid + off];
        __syncthreads();
    }
    float rstd = rsqrtf(red[0] * (1.f / H) + 1e-5f);
    __syncthreads();
    float fp = 0.f;
#pragma unroll
    for (int r = 0; r < 4; r++) {
        int h = r*256 + tid;
        float y = (hv[r] - mu) * rstd * ln_g[h] + ln_b[h];
        fp += y * W_fin[h];
    }
    red[tid] = fp; __syncthreads();
    for (int off = 128; off > 0; off >>= 1) {
        if (tid < off) red[tid] += red[tid + off];
        __syncthreads();
    }
    if (tid == 0) out[OFF_FIN + b] = red[0] + b_fin[0];
}

// ---------------------------------------------------------------------------
extern "C" void kernel_launch(void* const* d_in, const int* in_sizes, int n_in,
                              void* d_out, int out_size)
{
    const float* x      = (const float*)d_in[0];
    const float* h0     = (const float*)d_in[1];
    const float* c0     = (const float*)d_in[2];
    const float* enc    = (const float*)d_in[3];
    const float* W_enc  = (const float*)d_in[4];
    const float* W_dec  = (const float*)d_in[5];
    const float* w_val  = (const float*)d_in[6];
    const float* W_gate = (const float*)d_in[7];
    const float* events = (const float*)d_in[8];
    const float* W_ih   = (const float*)d_in[9];
    const float* W_hh   = (const float*)d_in[10];
    const float* b_ih   = (const float*)d_in[11];
    const float* b_hh   = (const float*)d_in[12];
    const float* ln_g   = (const float*)d_in[13];
    const float* ln_b   = (const float*)d_in[14];
    const float* W_fin  = (const float*)d_in[15];
    const float* b_fin  = (const float*)d_in[16];
    float* out = (float*)d_out;

    void* p;
    cudaGetSymbolAddress(&p, g_dec_proj); float* dec_proj = (float*)p;
    cudaGetSymbolAddress(&p, g_context);  float* context  = (float*)p;
    cudaGetSymbolAddress(&p, g_gates);    float* gates    = (float*)p;

    k_zero<<<256, 256>>>();

    // dec_proj = h0 @ W_dec^T    [64,1024] x [1024,1024]
    k_gemm64<<<dim3(16, 4), 256>>>(h0, H, W_dec, H, dec_proj, H, 256, H);

    // fused scores = sum_g w_val * tanh(enc @ W_enc^T + dec_proj)
    k_attn_scores<<<dim3(B * S / 128, H / 64), 256>>>(enc, W_enc, w_val);

    k_softmax<<<B, 256>>>(out);
    k_context<<<dim3(B, H / 256), 256>>>(enc, out);
    k_sim<<<B, 320>>>(events, W_gate, out);

    k_gates_init<<<dim3(B, 16), 256>>>(x, W_ih, b_ih, b_hh);
    // gates += context @ W_ih[:, :1024]^T
    k_gemm64<<<dim3(G4 / 64, 4), 256>>>(context, H, W_ih, LSTM_IN, gates, G4, 256, H);
    // gates += h0 @ W_hh^T
    k_gemm64<<<dim3(G4 / 64, 4), 256>>>(h0, H, W_hh, H, gates, G4, 256, H);

    k_lstm_final<<<B, 256>>>(c0, ln_g, ln_b, W_fin, b_fin, out);
}

// round 2
// speedup vs baseline: 2.9127x; 2.9127x over previous
#include <cuda_runtime.h>
#include <math.h>
#include <stdint.h>

#define B 64
#define S 512
#define H 1024
#define E 10
#define G4 4096
#define LSTM_IN 1035

// output packing offsets (flattened pytree order)
#define OFF_FIN 0
#define OFF_H   64
#define OFF_C   (64 + B*H)
#define OFF_A   (64 + 2*B*H)
#define OFF_S   (64 + 2*B*H + B*S)

// scratch (no allocation allowed)
__device__ float g_dec_proj[B*H];
__device__ float g_scores[B*S];
__device__ float g_context[B*H];
__device__ float g_gates[B*G4];
__device__ float g_sim[B*E];

__device__ __forceinline__ float sigmoidf_(float x) { return 1.f / (1.f + expf(-x)); }

__device__ __forceinline__ uint32_t f2tf32(float x) {
    uint32_t r;
    asm("cvt.rna.tf32.f32 %0, %1;" : "=r"(r) : "f"(x));
    return r;
}

__device__ __forceinline__ void mma_tf32(float c[4], const uint32_t a[4], const uint32_t b[2]) {
    asm volatile(
        "mma.sync.aligned.m16n8k8.row.col.f32.tf32.tf32.f32 "
        "{%0,%1,%2,%3}, {%4,%5,%6,%7}, {%8,%9}, {%0,%1,%2,%3};\n"
        : "+f"(c[0]), "+f"(c[1]), "+f"(c[2]), "+f"(c[3])
        : "r"(a[0]), "r"(a[1]), "r"(a[2]), "r"(a[3]), "r"(b[0]), "r"(b[1]));
}

// ---------------------------------------------------------------------------
__global__ void k_zero() {
    int i = blockIdx.x * blockDim.x + threadIdx.x;
    if (i < B*H) g_dec_proj[i] = 0.f;
    if (i < B*S) g_scores[i] = 0.f;
}

// ---------------------------------------------------------------------------
// Generic 64-row GEMM: C[64, N] += A[64, K] * W[N, ldw]^T   (fp32 SIMT)
// grid = (N/64, K/kChunk), block = 256.  Thread tile 4x4.
// ---------------------------------------------------------------------------
__global__ void __launch_bounds__(256) k_gemm64(
    const float* __restrict__ A, int lda,
    const float* __restrict__ W, int ldw,
    float* __restrict__ C, int ldc,
    int kChunk, int K)
{
    __shared__ float As[16][68];
    __shared__ float Ws[16][68];
    int tid = threadIdx.x;
    int nBase = blockIdx.x * 64;
    int kb = blockIdx.y * kChunk;
    int ke = min(kb + kChunk, K);
    int tx = tid & 15, ty = tid >> 4;
    int lm = tid >> 2;
    int lk = (tid & 3) * 4;

    float acc[4][4];
#pragma unroll
    for (int i = 0; i < 4; i++)
#pragma unroll
        for (int j = 0; j < 4; j++) acc[i][j] = 0.f;

    for (int k0 = kb; k0 < ke; k0 += 16) {
#pragma unroll
        for (int j = 0; j < 4; j++)
            As[lk + j][lm] = A[(size_t)lm * lda + k0 + lk + j];
#pragma unroll
        for (int j = 0; j < 4; j++)
            Ws[lk + j][lm] = W[(size_t)(nBase + lm) * ldw + k0 + lk + j];
        __syncthreads();
#pragma unroll
        for (int kk = 0; kk < 16; kk++) {
            float a[4], w[4];
#pragma unroll
            for (int i = 0; i < 4; i++) a[i] = As[kk][ty*4 + i];
#pragma unroll
            for (int j = 0; j < 4; j++) w[j] = Ws[kk][tx*4 + j];
#pragma unroll
            for (int i = 0; i < 4; i++)
#pragma unroll
                for (int j = 0; j < 4; j++) acc[i][j] += a[i] * w[j];
        }
        __syncthreads();
    }
#pragma unroll
    for (int i = 0; i < 4; i++)
#pragma unroll
        for (int j = 0; j < 4; j++)
            atomicAdd(&C[(size_t)(ty*4 + i) * ldc + nBase + tx*4 + j], acc[i][j]);
}

// ---------------------------------------------------------------------------
// TF32 tensor-core fused attention-score GEMM.
//   scores[b,s] += sum_{g in tile} w_val[g] * tanh( dec_proj[b,g] +
//                       sum_h enc[b,s,h] * W_enc[g,h] )
// Block tile: 128(bs) x 128(g) x K, BK=32.  8 warps as 2M x 4N, warp tile 64x32.
// grid = (H/128 (g fastest, L2 reuse of enc), B*S/128)
// ---------------------------------------------------------------------------
__global__ void __launch_bounds__(256) k_attn_mma(
    const float* __restrict__ enc,
    const float* __restrict__ Wenc,
    const float* __restrict__ w_val)
{
    __shared__ float As[128][36];   // [m][k], stride 36 -> bank (4r+c)%32, conflict-free
    __shared__ float Bs[128][36];   // [n(g)][k]

    int tid  = threadIdx.x;
    int lane = tid & 31, warp = tid >> 5;
    int warpM = warp & 1;        // 0..1  (64 rows each)
    int warpN = warp >> 1;       // 0..3  (32 g each)
    int group = lane >> 2;       // 0..7
    int tid4  = lane & 3;        // 0..3

    int gBase   = blockIdx.x * 128;
    int rowBase = blockIdx.y * 128;

    const float* Aptr = enc  + (size_t)rowBase * H;
    const float* Bptr = Wenc + (size_t)gBase   * H;

    int lr = tid >> 3;          // 0..31
    int lc = (tid & 7) * 4;     // 0..28

    float4 aReg[4], bReg[4];
#pragma unroll
    for (int r = 0; r < 4; r++) {
        aReg[r] = *(const float4*)(Aptr + (size_t)(lr + 32*r) * H + lc);
        bReg[r] = *(const float4*)(Bptr + (size_t)(lr + 32*r) * H + lc);
    }

    float acc[4][4][4];     // [mi 4x m16][ni 4x n8][c0..c3]
#pragma unroll
    for (int mi = 0; mi < 4; mi++)
#pragma unroll
        for (int ni = 0; ni < 4; ni++)
#pragma unroll
            for (int q = 0; q < 4; q++) acc[mi][ni][q] = 0.f;

    for (int k0 = 0; k0 < H; k0 += 32) {
        // store tile (converted to tf32 bits) to smem
#pragma unroll
        for (int r = 0; r < 4; r++) {
            uint4 av = make_uint4(f2tf32(aReg[r].x), f2tf32(aReg[r].y),
                                  f2tf32(aReg[r].z), f2tf32(aReg[r].w));
            uint4 bv = make_uint4(f2tf32(bReg[r].x), f2tf32(bReg[r].y),
                                  f2tf32(bReg[r].z), f2tf32(bReg[r].w));
            *(uint4*)&As[lr + 32*r][lc] = av;
            *(uint4*)&Bs[lr + 32*r][lc] = bv;
        }
        __syncthreads();

        if (k0 + 32 < H) {
#pragma unroll
            for (int r = 0; r < 4; r++) {
                aReg[r] = *(const float4*)(Aptr + (size_t)(lr + 32*r) * H + k0 + 32 + lc);
                bReg[r] = *(const float4*)(Bptr + (size_t)(lr + 32*r) * H + k0 + 32 + lc);
            }
        }

#pragma unroll
        for (int k8 = 0; k8 < 4; k8++) {
            int kk = k8 * 8;
            uint32_t afr[4][4], bfr[4][2];
#pragma unroll
            for (int mi = 0; mi < 4; mi++) {
                int m = warpM*64 + mi*16 + group;
                afr[mi][0] = __float_as_uint(As[m    ][kk + tid4    ]);
                afr[mi][1] = __float_as_uint(As[m + 8][kk + tid4    ]);
                afr[mi][2] = __float_as_uint(As[m    ][kk + tid4 + 4]);
                afr[mi][3] = __float_as_uint(As[m + 8][kk + tid4 + 4]);
            }
#pragma unroll
            for (int ni = 0; ni < 4; ni++) {
                int n = warpN*32 + ni*8 + group;
                bfr[ni][0] = __float_as_uint(Bs[n][kk + tid4    ]);
                bfr[ni][1] = __float_as_uint(Bs[n][kk + tid4 + 4]);
            }
#pragma unroll
            for (int mi = 0; mi < 4; mi++)
#pragma unroll
                for (int ni = 0; ni < 4; ni++)
                    mma_tf32(acc[mi][ni], afr[mi], bfr[ni]);
        }
        __syncthreads();
    }

    // epilogue: tanh + w_val dot over this warp's 8 g-columns per thread
    int b = rowBase / S;
    float wv[8], dp[8];
#pragma unroll
    for (int ni = 0; ni < 4; ni++)
#pragma unroll
        for (int q = 0; q < 2; q++) {
            int g = gBase + warpN*32 + ni*8 + 2*tid4 + q;
            wv[ni*2 + q] = w_val[g];
            dp[ni*2 + q] = g_dec_proj[b*H + g];
        }

#pragma unroll
    for (int mi = 0; mi < 4; mi++) {
        float p0 = 0.f, p1 = 0.f;
#pragma unroll
        for (int ni = 0; ni < 4; ni++)
#pragma unroll
            for (int q = 0; q < 2; q++) {
                int j = ni*2 + q;
                p0 += wv[j] * tanhf(acc[mi][ni][q    ] + dp[j]);
                p1 += wv[j] * tanhf(acc[mi][ni][2 + q] + dp[j]);
            }
        p0 += __shfl_down_sync(0xffffffffu, p0, 2, 4);
        p0 += __shfl_down_sync(0xffffffffu, p0, 1, 4);
        p1 += __shfl_down_sync(0xffffffffu, p1, 2, 4);
        p1 += __shfl_down_sync(0xffffffffu, p1, 1, 4);
        if (tid4 == 0) {
            int row = rowBase + warpM*64 + mi*16 + group;
            atomicAdd(&g_scores[row    ], p0);
            atomicAdd(&g_scores[row + 8], p1);
        }
    }
}

// ---------------------------------------------------------------------------
__global__ void k_softmax(float* __restrict__ out)
{
    int b = blockIdx.x, tid = threadIdx.x;
    __shared__ float red[256];
    float s0 = g_scores[b*S + tid];
    float s1 = g_scores[b*S + 256 + tid];
    red[tid] = fmaxf(s0, s1);
    __syncthreads();
    for (int off = 128; off > 0; off >>= 1) {
        if (tid < off) red[tid] = fmaxf(red[tid], red[tid + off]);
        __syncthreads();
    }
    float m = red[0];
    __syncthreads();
    float e0 = expf(s0 - m), e1 = expf(s1 - m);
    red[tid] = e0 + e1;
    __syncthreads();
    for (int off = 128; off > 0; off >>= 1) {
        if (tid < off) red[tid] += red[tid + off];
        __syncthreads();
    }
    float inv = 1.f / red[0];
    out[OFF_A + b*S + tid]       = e0 * inv;
    out[OFF_A + b*S + 256 + tid] = e1 * inv;
}

// ---------------------------------------------------------------------------
__global__ void k_context(const float* __restrict__ enc, const float* __restrict__ out)
{
    int b = blockIdx.x;
    int h = blockIdx.y * 256 + threadIdx.x;
    __shared__ float w[S];
    for (int s = threadIdx.x; s < S; s += 256) w[s] = out[OFF_A + b*S + s];
    __syncthreads();
    const float* p = enc + (size_t)b * S * H + h;
    float a0 = 0.f, a1 = 0.f, a2 = 0.f, a3 = 0.f;
#pragma unroll 4
    for (int s = 0; s < S; s += 4) {
        a0 += w[s]     * p[(size_t)s * H];
        a1 += w[s + 1] * p[(size_t)(s + 1) * H];
        a2 += w[s + 2] * p[(size_t)(s + 2) * H];
        a3 += w[s + 3] * p[(size_t)(s + 3) * H];
    }
    g_context[b*H + h] = (a0 + a1) + (a2 + a3);
}

// ---------------------------------------------------------------------------
__global__ void k_sim(const float* __restrict__ events,
                      const float* __restrict__ W_gate,
                      float* __restrict__ out)
{
    int b = blockIdx.x;
    int tid = threadIdx.x, warp = tid >> 5, lane = tid & 31;
    __shared__ float t[E];
    if (warp < E) {
        float acc = 0.f;
        for (int h = lane; h < H; h += 32)
            acc += g_context[b*H + h] * events[warp*H + h];
#pragma unroll
        for (int off = 16; off > 0; off >>= 1)
            acc += __shfl_down_sync(0xffffffffu, acc, off);
        if (lane == 0) t[warp] = acc;
    }
    __syncthreads();
    if (tid < E) {
        float s = 0.f;
#pragma unroll
        for (int e = 0; e < E; e++) s += t[e] * W_gate[tid*E + e];
        g_sim[b*E + tid] = s;
        out[OFF_S + b*E + tid] = s;
    }
}

// ---------------------------------------------------------------------------
__global__ void k_gates_init(const float* __restrict__ x,
                             const float* __restrict__ W_ih,
                             const float* __restrict__ b_ih,
                             const float* __restrict__ b_hh)
{
    int b = blockIdx.x;
    int j = blockIdx.y * 256 + threadIdx.x;
    const float* wr = W_ih + (size_t)j * LSTM_IN;
    float v = b_ih[j] + b_hh[j] + x[b] * wr[1034];
#pragma unroll
    for (int e = 0; e < E; e++) v += g_sim[b*E + e] * wr[1024 + e];
    g_gates[b*G4 + j] = v;
}

// ---------------------------------------------------------------------------
__global__ void k_lstm_final(const float* __restrict__ c0,
                             const float* __restrict__ ln_g,
                             const float* __restrict__ ln_b,
                             const float* __restrict__ W_fin,
                             const float* __restrict__ b_fin,
                             float* __restrict__ out)
{
    int b = blockIdx.x, tid = threadIdx.x;
    __shared__ float red[256];
    float hv[4];
    float sum = 0.f;
#pragma unroll
    for (int r = 0; r < 4; r++) {
        int h = r*256 + tid;
        float ig = g_gates[b*G4 + h];
        float fg = g_gates[b*G4 + 1024 + h];
        float gg = g_gates[b*G4 + 2048 + h];
        float og = g_gates[b*G4 + 3072 + h];
        float cn = sigmoidf_(fg) * c0[b*H + h] + sigmoidf_(ig) * tanhf(gg);
        float hn = sigmoidf_(og) * tanhf(cn);
        out[OFF_H + b*H + h] = hn;
        out[OFF_C + b*H + h] = cn;
        hv[r] = hn;
        sum += hn;
    }
    red[tid] = sum; __syncthreads();
    for (int off = 128; off > 0; off >>= 1) {
        if (tid < off) red[tid] += red[tid + off];
        __syncthreads();
    }
    float mu = red[0] * (1.f / H);
    __syncthreads();
    float sq = 0.f;
#pragma unroll
    for (int r = 0; r < 4; r++) { float d = hv[r] - mu; sq += d * d; }
    red[tid] = sq; __syncthreads();
    for (int off = 128; off > 0; off >>= 1) {
        if (tid < off) red[tid] += red[tid + off];
        __syncthreads();
    }
    float rstd = rsqrtf(red[0] * (1.f / H) + 1e-5f);
    __syncthreads();
    float fp = 0.f;
#pragma unroll
    for (int r = 0; r < 4; r++) {
        int h = r*256 + tid;
        float y = (hv[r] - mu) * rstd * ln_g[h] + ln_b[h];
        fp += y * W_fin[h];
    }
    red[tid] = fp; __syncthreads();
    for (int off = 128; off > 0; off >>= 1) {
        if (tid < off) red[tid] += red[tid + off];
        __syncthreads();
    }
    if (tid == 0) out[OFF_FIN + b] = red[0] + b_fin[0];
}

// ---------------------------------------------------------------------------
extern "C" void kernel_launch(void* const* d_in, const int* in_sizes, int n_in,
                              void* d_out, int out_size)
{
    const float* x      = (const float*)d_in[0];
    const float* h0     = (const float*)d_in[1];
    const float* c0     = (const float*)d_in[2];
    const float* enc    = (const float*)d_in[3];
    const float* W_enc  = (const float*)d_in[4];
    const float* W_dec  = (const float*)d_in[5];
    const float* w_val  = (const float*)d_in[6];
    const float* W_gate = (const float*)d_in[7];
    const float* events = (const float*)d_in[8];
    const float* W_ih   = (const float*)d_in[9];
    const float* W_hh   = (const float*)d_in[10];
    const float* b_ih   = (const float*)d_in[11];
    const float* b_hh   = (const float*)d_in[12];
    const float* ln_g   = (const float*)d_in[13];
    const float* ln_b   = (const float*)d_in[14];
    const float* W_fin  = (const float*)d_in[15];
    const float* b_fin  = (const float*)d_in[16];
    float* out = (float*)d_out;

    void* p;
    cudaGetSymbolAddress(&p, g_dec_proj); float* dec_proj = (float*)p;
    cudaGetSymbolAddress(&p, g_context);  float* context  = (float*)p;
    cudaGetSymbolAddress(&p, g_gates);    float* gates    = (float*)p;

    k_zero<<<256, 256>>>();

    // dec_proj = h0 @ W_dec^T
    k_gemm64<<<dim3(16, 4), 256>>>(h0, H, W_dec, H, dec_proj, H, 256, H);

    // fused scores via TF32 tensor cores; g-tile fastest for enc L2 reuse
    k_attn_mma<<<dim3(H / 128, B * S / 128), 256>>>(enc, W_enc, w_val);

    k_softmax<<<B, 256>>>(out);
    k_context<<<dim3(B, H / 256), 256>>>(enc, out);
    k_sim<<<B, 320>>>(events, W_gate, out);

    k_gates_init<<<dim3(B, 16), 256>>>(x, W_ih, b_ih, b_hh);
    k_gemm64<<<dim3(G4 / 64, 4), 256>>>(context, H, W_ih, LSTM_IN, gates, G4, 256, H);
    k_gemm64<<<dim3(G4 / 64, 4), 256>>>(h0, H, W_hh, H, gates, G4, 256, H);

    k_lstm_final<<<B, 256>>>(c0, ln_g, ln_b, W_fin, b_fin, out);
}